// round 15
// baseline (speedup 1.0000x reference)
#include <cuda_runtime.h>
#include <cuda_fp16.h>
#include <math.h>
#include <cstdint>

#define BB   2
#define TT   2048
#define BT   4096
#define DIMC 1024
#define NH   16
#define HD   64
#define HID  4096
#define QKVD 3072
#define EPSV 1e-6f

// ---------------- scratch ----------------------------------------------------
__device__ __half g_xn  [BT * DIMC];
__device__ __half g_qkv [BT * QKVD];
__device__ float  g_x1  [BT * DIMC];
__device__ __half g_h   [BT * HID];
__device__ __half g_ao  [BT * DIMC];
__device__ __half g_wqkv[DIMC * QKVD];   // [k][n] packed wq|wk|wv (wq scaled 1/8)
__device__ __half g_wou [DIMC * DIMC];
__device__ __half g_w1u [DIMC * HID];
__device__ __half g_w2u [HID * DIMC];

// ---------------- helpers -----------------------------------------------------
__device__ __forceinline__ unsigned h2pack(float lo, float hi) {
    __half2 t = __floats2half2_rn(lo, hi);
    return *(unsigned*)&t;
}
__device__ __forceinline__ uint32_t smem_u32(const void* p) {
    uint32_t a;
    asm("{ .reg .u64 t; cvta.to.shared.u64 t, %1; cvt.u32.u64 %0, t; }"
        : "=r"(a) : "l"(p));
    return a;
}
__device__ __forceinline__ void mma16(float* d, const unsigned* a, const unsigned* b) {
    asm volatile(
        "mma.sync.aligned.m16n8k16.row.col.f32.f16.f16.f32 "
        "{%0,%1,%2,%3}, {%4,%5,%6,%7}, {%8,%9}, {%0,%1,%2,%3};"
        : "+f"(d[0]), "+f"(d[1]), "+f"(d[2]), "+f"(d[3])
        : "r"(a[0]), "r"(a[1]), "r"(a[2]), "r"(a[3]), "r"(b[0]), "r"(b[1]));
}
__device__ __forceinline__ void ldsm4(uint32_t addr, unsigned* r) {
    asm volatile("ldmatrix.sync.aligned.m8n8.x4.shared.b16 {%0,%1,%2,%3}, [%4];"
        : "=r"(r[0]), "=r"(r[1]), "=r"(r[2]), "=r"(r[3]) : "r"(addr));
}
__device__ __forceinline__ void ldsm4t(uint32_t addr, unsigned* r) {
    asm volatile("ldmatrix.sync.aligned.m8n8.x4.trans.shared.b16 {%0,%1,%2,%3}, [%4];"
        : "=r"(r[0]), "=r"(r[1]), "=r"(r[2]), "=r"(r[3]) : "r"(addr));
}
__device__ __forceinline__ void cpasync16(uint32_t dst, const void* src) {
    asm volatile("cp.async.cg.shared.global [%0], [%1], 16;"
        :: "r"(dst), "l"(__cvta_generic_to_global(src)));
}
#define CP_COMMIT asm volatile("cp.async.commit_group;" ::: "memory")

// ---------------- fused prep: rmsnorm#1 + pack qkv -----------------------------
__global__ void prep_kernel(const float* __restrict__ x, const float* __restrict__ ga,
                            __half* __restrict__ xn,
                            const float* __restrict__ wq, const float* __restrict__ wk,
                            const float* __restrict__ wv, __half* __restrict__ wqkv) {
    const int nW = DIMC * DIMC;
    int bid = blockIdx.x;
    int tid = threadIdx.x;
    if (bid < BT) {
        const float* xr = x + (size_t)bid * DIMC;
        float4 xv = *(const float4*)(xr + tid * 4);
        float s = xv.x * xv.x + xv.y * xv.y + xv.z * xv.z + xv.w * xv.w;
        #pragma unroll
        for (int off = 16; off; off >>= 1) s += __shfl_xor_sync(0xFFFFFFFFu, s, off);
        __shared__ float ws[8];
        __shared__ float snorm;
        if ((tid & 31) == 0) ws[tid >> 5] = s;
        __syncthreads();
        if (tid == 0) {
            float t = 0.f;
            #pragma unroll
            for (int i = 0; i < 8; i++) t += ws[i];
            snorm = rsqrtf(t * (1.0f / DIMC) + EPSV);
        }
        __syncthreads();
        float n = snorm;
        float4 gv = *(const float4*)(ga + tid * 4);
        uint2 u;
        u.x = h2pack(xv.x * n * gv.x, xv.y * n * gv.y);
        u.y = h2pack(xv.z * n * gv.z, xv.w * n * gv.w);
        *(uint2*)(xn + (size_t)bid * DIMC + tid * 4) = u;
    } else {
        int i = ((bid - BT) * 256 + tid) * 16;
        int w = i / nW, li = i - w * nW;
        const float* src = (w == 0) ? wq : (w == 1) ? wk : wv;
        float scale = (w == 0) ? 0.125f : 1.0f;
        int r = li >> 10, c = li & 1023;
        __half* drow = wqkv + (size_t)r * QKVD + w * DIMC + c;
        float4 v0 = *(const float4*)(src + li);
        float4 v1 = *(const float4*)(src + li + 4);
        float4 v2 = *(const float4*)(src + li + 8);
        float4 v3 = *(const float4*)(src + li + 12);
        uint4 a, b;
        a.x = h2pack(v0.x * scale, v0.y * scale); a.y = h2pack(v0.z * scale, v0.w * scale);
        a.z = h2pack(v1.x * scale, v1.y * scale); a.w = h2pack(v1.z * scale, v1.w * scale);
        b.x = h2pack(v2.x * scale, v2.y * scale); b.y = h2pack(v2.z * scale, v2.w * scale);
        b.z = h2pack(v3.x * scale, v3.y * scale); b.w = h2pack(v3.z * scale, v3.w * scale);
        *(uint4*)drow = a;
        *(uint4*)(drow + 8) = b;
    }
}

// ---------------- RMSNorm (half output) ----------------------------------------
__global__ void rmsnorm_kernel(const float* __restrict__ x,
                               const float* __restrict__ g,
                               __half* __restrict__ y) {
    int row = blockIdx.x;
    int tid = threadIdx.x;
    const float* xr = x + (size_t)row * DIMC;
    float4 xv = *(const float4*)(xr + tid * 4);
    float s = xv.x * xv.x + xv.y * xv.y + xv.z * xv.z + xv.w * xv.w;
    #pragma unroll
    for (int off = 16; off; off >>= 1) s += __shfl_xor_sync(0xFFFFFFFFu, s, off);
    __shared__ float ws[8];
    __shared__ float snorm;
    if ((tid & 31) == 0) ws[tid >> 5] = s;
    __syncthreads();
    if (tid == 0) {
        float t = 0.f;
        #pragma unroll
        for (int i = 0; i < 8; i++) t += ws[i];
        snorm = rsqrtf(t * (1.0f / DIMC) + EPSV);
    }
    __syncthreads();
    float n = snorm;
    float4 gv = *(const float4*)(g + tid * 4);
    uint2 u;
    u.x = h2pack(xv.x * n * gv.x, xv.y * n * gv.y);
    u.y = h2pack(xv.z * n * gv.z, xv.w * n * gv.w);
    *(uint2*)(y + (size_t)row * DIMC + tid * 4) = u;
}

// ---------------- FP16 GEMM 128x128, 128 threads, warp tile 64x64 --------------
// stage (32KB): A [128 m][64 k] half SW @ +0 (16KB), B [64 k][128 n] @ +16384
#define GSTAGE 32768
#define G_SMEM (3 * GSTAGE)
// mode bits: 1 = silu, 2 = half output
__global__ __launch_bounds__(128, 2)
void gemm_f16(const __half* __restrict__ A, const __half* __restrict__ B,
              float* __restrict__ C, const float* __restrict__ res,
              int M, int N, int K, int mode) {
    extern __shared__ char smc[];
    const uint32_t sbase = smem_u32(smc);
    const int tid = threadIdx.x;
    const int warp = tid >> 5, lane = tid & 31;
    const int lg = lane >> 2, ltg = lane & 3;
    const int wm = warp >> 1, wn = warp & 1;     // 2x2 warps
    const int bm0 = blockIdx.y * 128, bn0 = blockIdx.x * 128;

    // A loader: rows arow0 + 16i (i<8), 16B chunk ac
    const int arow0 = tid >> 3, ac = tid & 7;
    const __half* Agp = A + (size_t)(bm0 + arow0) * K + ac * 8;
    const int asw = (ac * 16) ^ ((arow0 & 7) << 4);
    // B loader: k rows brow0 + 8i (i<8), 16B chunk bc (row 256B)
    const int brow0 = tid >> 4, bc = tid & 15;
    const __half* Bgp = B + (size_t)brow0 * N + bn0 + bc * 8;
    const int bsw = (bc * 16) ^ ((brow0 & 7) << 4);

    const int mat = lane >> 3, mrow = lane & 7;
    int aoff[4], boff[4];
    #pragma unroll
    for (int mt = 0; mt < 4; mt++) {
        int row = wm * 64 + mt * 16 + (mat & 1) * 8 + mrow;
        aoff[mt] = row * 128 + (((mat >> 1) << 4) ^ ((row & 7) << 4));
    }
    #pragma unroll
    for (int p = 0; p < 4; p++) {
        int kr = (mat & 1) * 8 + mrow;
        int nb = wn * 128 + p * 32 + ((mat >> 1) << 4);  // byte offset in 256B row
        boff[p] = kr * 256 + (nb ^ ((kr & 7) << 4));
    }

    float acc[4][8][4];
    #pragma unroll
    for (int mt = 0; mt < 4; mt++)
        #pragma unroll
        for (int nt = 0; nt < 8; nt++)
            #pragma unroll
            for (int r = 0; r < 4; r++) acc[mt][nt][r] = 0.f;

    auto loadAB = [&](int kt, int slot) {
        uint32_t da = sbase + slot * GSTAGE;
        uint32_t db = da + 16384;
        #pragma unroll
        for (int i = 0; i < 8; i++)
            cpasync16(da + (arow0 + i * 16) * 128 + asw,
                      Agp + (size_t)kt * 64 + (size_t)i * 16 * K);
        #pragma unroll
        for (int i = 0; i < 8; i++)
            cpasync16(db + (brow0 + i * 8) * 256 + bsw,
                      Bgp + (size_t)(kt * 64 + i * 8) * N);
    };

    const int nkt = K >> 6;
    loadAB(0, 0); CP_COMMIT;
    loadAB(1, 1); CP_COMMIT;

    int slot = 0;
    for (int kt = 0; kt < nkt; kt++) {
        asm volatile("cp.async.wait_group 1;" ::: "memory");
        __syncthreads();
        if (kt + 2 < nkt) {
            int s2 = slot + 2; if (s2 >= 3) s2 -= 3;
            loadAB(kt + 2, s2);
            CP_COMMIT;
        }
        uint32_t sa = sbase + slot * GSTAGE;
        uint32_t sb = sa + 16384;
        #pragma unroll
        for (int kk = 0; kk < 4; kk++) {
            unsigned af[4][4], bf[4][4];
            #pragma unroll
            for (int mt = 0; mt < 4; mt++)
                ldsm4(sa + (aoff[mt] ^ (kk << 5)), af[mt]);
            #pragma unroll
            for (int p = 0; p < 4; p++)
                ldsm4t(sb + boff[p] + (kk << 12), bf[p]);
            #pragma unroll
            for (int mt = 0; mt < 4; mt++)
                #pragma unroll
                for (int nt = 0; nt < 8; nt++)
                    mma16(acc[mt][nt], af[mt], &bf[nt >> 1][(nt & 1) * 2]);
        }
        if (++slot >= 3) slot = 0;
    }

    // epilogue: rows wm*64+mt*16+lg(+8), cols wn*64+nt*8+2*ltg
    #pragma unroll
    for (int mt = 0; mt < 4; mt++) {
        #pragma unroll
        for (int half = 0; half < 2; half++) {
            int r = bm0 + wm * 64 + mt * 16 + lg + half * 8;
            #pragma unroll
            for (int nt = 0; nt < 8; nt++) {
                int c = bn0 + wn * 64 + nt * 8 + 2 * ltg;
                float v0 = acc[mt][nt][half * 2 + 0];
                float v1 = acc[mt][nt][half * 2 + 1];
                if (mode & 1) {
                    v0 = v0 / (1.f + __expf(-v0));
                    v1 = v1 / (1.f + __expf(-v1));
                }
                if (res) {
                    float2 rv = *(const float2*)(res + (size_t)r * N + c);
                    v0 += rv.x; v1 += rv.y;
                }
                if (mode & 2) {
                    *(unsigned*)((__half*)C + (size_t)r * N + c) = h2pack(v0, v1);
                } else {
                    *(float2*)(C + (size_t)r * N + c) = make_float2(v0, v1);
                }
            }
        }
    }
}

// ---------------- Flash attention + fused wo/w1/w2 conversion ------------------
#define ATT_NBLK (BB * NH * (TT / 128))      // 512
__global__ __launch_bounds__(256, 2)
void attn_cvt_f16(const __half* __restrict__ QKV, __half* __restrict__ O,
                  const float* __restrict__ wo, const float* __restrict__ w1,
                  const float* __restrict__ w2,
                  __half* __restrict__ dwo, __half* __restrict__ dw1,
                  __half* __restrict__ dw2) {
    __shared__ __align__(16) char smA[16384];
    int bid = blockIdx.x;
    int tid = threadIdx.x;

    if (bid >= ATT_NBLK) {
        const int nW = DIMC * DIMC, nW4 = DIMC * HID;
        int i = ((bid - ATT_NBLK) * 256 + tid) * 16;
        const float* src;
        __half* dst;
        int li;
        if (i < nW)            { src = wo; dst = dwo; li = i; }
        else if (i < nW + nW4) { src = w1; dst = dw1; li = i - nW; }
        else                   { src = w2; dst = dw2; li = i - nW - nW4; }
        float4 v0 = *(const float4*)(src + li);
        float4 v1 = *(const float4*)(src + li + 4);
        float4 v2 = *(const float4*)(src + li + 8);
        float4 v3 = *(const float4*)(src + li + 12);
        uint4 a, b;
        a.x = h2pack(v0.x, v0.y); a.y = h2pack(v0.z, v0.w);
        a.z = h2pack(v1.x, v1.y); a.w = h2pack(v1.z, v1.w);
        b.x = h2pack(v2.x, v2.y); b.y = h2pack(v2.z, v2.w);
        b.z = h2pack(v3.x, v3.y); b.w = h2pack(v3.z, v3.w);
        *(uint4*)(dst + li) = a;
        *(uint4*)(dst + li + 8) = b;
        return;
    }

    int bh = bid & 31;
    int qt = (TT / 128 - 1) - (bid >> 5);
    char* Ksc = smA;
    char* Vsc = smA + 8192;
    const uint32_t ksb = smem_u32(Ksc);
    const uint32_t vsb = smem_u32(Vsc);

    int b = bh >> 4, h = bh & 15;
    int q0 = qt * 128;
    int warp = tid >> 5, lane = tid & 31;
    int g = lane >> 2, tg = lane & 3;
    int r0l = warp * 16 + g;
    const int mat = lane >> 3, mrow = lane & 7;
    int rmax = q0 + warp * 16 + 15;

    const __half* Qb = QKV + ((size_t)(b * TT + q0)) * QKVD + h * HD;
    const __half* Kb = QKV + ((size_t)(b * TT)) * QKVD + DIMC + h * HD;
    const __half* Vb = QKV + ((size_t)(b * TT)) * QKVD + 2 * DIMC + h * HD;

    unsigned qa[4][4];
    #pragma unroll
    for (int kk = 0; kk < 4; kk++) {
        qa[kk][0] = *(const unsigned*)(Qb + (size_t)r0l * QKVD + kk * 16 + 2 * tg);
        qa[kk][1] = *(const unsigned*)(Qb + (size_t)(r0l + 8) * QKVD + kk * 16 + 2 * tg);
        qa[kk][2] = *(const unsigned*)(Qb + (size_t)r0l * QKVD + kk * 16 + 8 + 2 * tg);
        qa[kk][3] = *(const unsigned*)(Qb + (size_t)(r0l + 8) * QKVD + kk * 16 + 8 + 2 * tg);
    }

    int boffK[4], voff[4];
    #pragma unroll
    for (int p = 0; p < 4; p++) {
        int n = p * 16 + (mat >> 1) * 8 + mrow;
        boffK[p] = n * 128 + ((((unsigned)(mat & 1)) << 4) ^ ((n & 7) << 4));
        int sr = (mat & 1) * 8 + mrow;
        int db = (2 * p + (mat >> 1)) * 16;
        voff[p] = sr * 128 + (db ^ ((sr & 7) << 4));
    }

    float oacc[8][4];
    #pragma unroll
    for (int nt = 0; nt < 8; nt++)
        #pragma unroll
        for (int r = 0; r < 4; r++) oacc[nt][r] = 0.f;
    float m0 = -1e30f, m1 = -1e30f, l0 = 0.f, l1 = 0.f;
    int r0g = q0 + r0l, r1g = r0g + 8;

    int send = q0 + 64;
    for (int s0 = 0; s0 <= send; s0 += 64) {
        for (int i = tid; i < 512; i += 256) {
            int r = i >> 3, c = i & 7;
            int sw = (c * 16) ^ ((r & 7) << 4);
            *(uint4*)(Ksc + r * 128 + sw) =
                *(const uint4*)(Kb + (size_t)(s0 + r) * QKVD + c * 8);
            *(uint4*)(Vsc + r * 128 + sw) =
                *(const uint4*)(Vb + (size_t)(s0 + r) * QKVD + c * 8);
        }
        __syncthreads();

        if (s0 <= rmax) {
            float sc[8][4];
            #pragma unroll
            for (int nt = 0; nt < 8; nt++)
                #pragma unroll
                for (int r = 0; r < 4; r++) sc[nt][r] = 0.f;
            #pragma unroll
            for (int kk = 0; kk < 4; kk++) {
                #pragma unroll
                for (int p = 0; p < 4; p++) {
                    unsigned bf[4];
                    ldsm4(ksb + (boffK[p] ^ (kk << 5)), bf);
                    mma16(sc[2 * p], qa[kk], bf);
                    mma16(sc[2 * p + 1], qa[kk], bf + 2);
                }
            }

            if (s0 + 63 > r0g) {
                #pragma unroll
                for (int nt = 0; nt < 8; nt++) {
                    int j = s0 + nt * 8 + 2 * tg;
                    if (j     > r0g) sc[nt][0] = -1e30f;
                    if (j + 1 > r0g) sc[nt][1] = -1e30f;
                    if (j     > r1g) sc[nt][2] = -1e30f;
                    if (j + 1 > r1g) sc[nt][3] = -1e30f;
                }
            }

            float mx0 = -1e30f, mx1 = -1e30f;
            #pragma unroll
            for (int nt = 0; nt < 8; nt++) {
                mx0 = fmaxf(mx0, fmaxf(sc[nt][0], sc[nt][1]));
                mx1 = fmaxf(mx1, fmaxf(sc[nt][2], sc[nt][3]));
            }
            mx0 = fmaxf(mx0, __shfl_xor_sync(0xFFFFFFFFu, mx0, 1));
            mx0 = fmaxf(mx0, __shfl_xor_sync(0xFFFFFFFFu, mx0, 2));
            mx1 = fmaxf(mx1, __shfl_xor_sync(0xFFFFFFFFu, mx1, 1));
            mx1 = fmaxf(mx1, __shfl_xor_sync(0xFFFFFFFFu, mx1, 2));
            float mn0 = fmaxf(m0, mx0), mn1 = fmaxf(m1, mx1);
            float al0 = __expf(m0 - mn0), al1 = __expf(m1 - mn1);
            float s0r = 0.f, s1r = 0.f;
            #pragma unroll
            for (int nt = 0; nt < 8; nt++) {
                sc[nt][0] = __expf(sc[nt][0] - mn0);
                sc[nt][1] = __expf(sc[nt][1] - mn0);
                sc[nt][2] = __expf(sc[nt][2] - mn1);
                sc[nt][3] = __expf(sc[nt][3] - mn1);
                s0r += sc[nt][0] + sc[nt][1];
                s1r += sc[nt][2] + sc[nt][3];
            }
            s0r += __shfl_xor_sync(0xFFFFFFFFu, s0r, 1);
            s0r += __shfl_xor_sync(0xFFFFFFFFu, s0r, 2);
            s1r += __shfl_xor_sync(0xFFFFFFFFu, s1r, 1);
            s1r += __shfl_xor_sync(0xFFFFFFFFu, s1r, 2);
            l0 = l0 * al0 + s0r;
            l1 = l1 * al1 + s1r;
            m0 = mn0; m1 = mn1;
            #pragma unroll
            for (int nt = 0; nt < 8; nt++) {
                oacc[nt][0] *= al0; oacc[nt][1] *= al0;
                oacc[nt][2] *= al1; oacc[nt][3] *= al1;
            }

            #pragma unroll
            for (int kk = 0; kk < 4; kk++) {
                unsigned pa[4];
                pa[0] = h2pack(sc[2 * kk][0],     sc[2 * kk][1]);
                pa[1] = h2pack(sc[2 * kk][2],     sc[2 * kk][3]);
                pa[2] = h2pack(sc[2 * kk + 1][0], sc[2 * kk + 1][1]);
                pa[3] = h2pack(sc[2 * kk + 1][2], sc[2 * kk + 1][3]);
                #pragma unroll
                for (int p = 0; p < 4; p++) {
                    unsigned bf[4];
                    ldsm4t(vsb + voff[p] + (kk << 11), bf);
                    mma16(oacc[2 * p], pa, bf);
                    mma16(oacc[2 * p + 1], pa, bf + 2);
                }
            }
        }
        __syncthreads();
    }

    float il0 = 1.f / l0, il1 = 1.f / l1;
    __half* Ob = O + ((size_t)(b * TT + q0 + r0l)) * DIMC + h * HD;
    #pragma unroll
    for (int nt = 0; nt < 8; nt++) {
        *(unsigned*)(Ob + nt * 8 + 2 * tg) =
            h2pack(oacc[nt][0] * il0, oacc[nt][1] * il0);
        *(unsigned*)(Ob + (size_t)8 * DIMC + nt * 8 + 2 * tg) =
            h2pack(oacc[nt][2] * il1, oacc[nt][3] * il1);
    }
}

// ---------------- launcher ----------------------------------------------------
extern "C" void kernel_launch(void* const* d_in, const int* in_sizes, int n_in,
                              void* d_out, int out_size) {
    const float* x  = (const float*)d_in[0];
    const float* wq = (const float*)d_in[2];
    const float* wk = (const float*)d_in[3];
    const float* wv = (const float*)d_in[4];
    const float* wo = (const float*)d_in[5];
    const float* w1 = (const float*)d_in[6];
    const float* w2 = (const float*)d_in[7];
    const float* ga = (const float*)d_in[8];
    const float* gf = (const float*)d_in[9];
    float* out = (float*)d_out;

    __half *xn, *qkv, *ao, *hb, *wqkv, *wou, *w1u, *w2u;
    float *x1;
    cudaGetSymbolAddress((void**)&xn,   g_xn);
    cudaGetSymbolAddress((void**)&qkv,  g_qkv);
    cudaGetSymbolAddress((void**)&ao,   g_ao);
    cudaGetSymbolAddress((void**)&x1,   g_x1);
    cudaGetSymbolAddress((void**)&hb,   g_h);
    cudaGetSymbolAddress((void**)&wqkv, g_wqkv);
    cudaGetSymbolAddress((void**)&wou,  g_wou);
    cudaGetSymbolAddress((void**)&w1u,  g_w1u);
    cudaGetSymbolAddress((void**)&w2u,  g_w2u);

    cudaFuncSetAttribute(gemm_f16,
                         cudaFuncAttributeMaxDynamicSharedMemorySize, G_SMEM);

    dim3 gQKV(QKVD / 128, BT / 128);  // (24, 32)
    dim3 gN1(DIMC / 128, BT / 128);   // (8, 32)
    dim3 gN4(HID  / 128, BT / 128);   // (32, 32)

    const int nW = DIMC * DIMC, nW4 = DIMC * HID;
    const int cvtBlocks = (nW + 2 * nW4) / 4096;       // 2304

    prep_kernel<<<BT + (3 * nW) / 4096, 256>>>(x, ga, xn, wq, wk, wv, wqkv);
    gemm_f16<<<gQKV, 128, G_SMEM>>>(xn, wqkv, (float*)qkv, nullptr, BT, QKVD, DIMC, 2);
    attn_cvt_f16<<<ATT_NBLK + cvtBlocks, 256>>>(qkv, ao, wo, w1, w2, wou, w1u, w2u);
    gemm_f16<<<gN1, 128, G_SMEM>>>(ao, wou, x1, x, BT, DIMC, DIMC, 0);
    rmsnorm_kernel<<<BT, 256>>>(x1, gf, xn);
    gemm_f16<<<gN4, 128, G_SMEM>>>(xn, w1u, (float*)hb, nullptr, BT, HID, DIMC, 3);
    gemm_f16<<<gN1, 128, G_SMEM>>>(hb, w2u, out, x1, BT, DIMC, HID, 0);
}

// round 16
// speedup vs baseline: 1.0732x; 1.0732x over previous
#include <cuda_runtime.h>
#include <cuda_fp16.h>
#include <math.h>
#include <cstdint>

#define BB   2
#define TT   2048
#define BT   4096
#define DIMC 1024
#define NH   16
#define HD   64
#define HID  4096
#define QKVD 3072
#define EPSV 1e-6f

// ---------------- scratch ----------------------------------------------------
__device__ __half g_xn  [BT * DIMC];
__device__ __half g_qkv [BT * QKVD];
__device__ __half g_x1  [BT * DIMC];     // fp16 residual stream
__device__ __half g_h   [BT * HID];
__device__ __half g_ao  [BT * DIMC];
__device__ __half g_wqkv[DIMC * QKVD];   // [k][n] packed wq|wk|wv (wq scaled 1/8)
__device__ __half g_wou [DIMC * DIMC];
__device__ __half g_w1u [DIMC * HID];
__device__ __half g_w2u [HID * DIMC];

// ---------------- helpers -----------------------------------------------------
__device__ __forceinline__ unsigned h2pack(float lo, float hi) {
    __half2 t = __floats2half2_rn(lo, hi);
    return *(unsigned*)&t;
}
__device__ __forceinline__ uint32_t smem_u32(const void* p) {
    uint32_t a;
    asm("{ .reg .u64 t; cvta.to.shared.u64 t, %1; cvt.u32.u64 %0, t; }"
        : "=r"(a) : "l"(p));
    return a;
}
__device__ __forceinline__ void mma16(float* d, const unsigned* a, const unsigned* b) {
    asm volatile(
        "mma.sync.aligned.m16n8k16.row.col.f32.f16.f16.f32 "
        "{%0,%1,%2,%3}, {%4,%5,%6,%7}, {%8,%9}, {%0,%1,%2,%3};"
        : "+f"(d[0]), "+f"(d[1]), "+f"(d[2]), "+f"(d[3])
        : "r"(a[0]), "r"(a[1]), "r"(a[2]), "r"(a[3]), "r"(b[0]), "r"(b[1]));
}
__device__ __forceinline__ void ldsm4(uint32_t addr, unsigned* r) {
    asm volatile("ldmatrix.sync.aligned.m8n8.x4.shared.b16 {%0,%1,%2,%3}, [%4];"
        : "=r"(r[0]), "=r"(r[1]), "=r"(r[2]), "=r"(r[3]) : "r"(addr));
}
__device__ __forceinline__ void ldsm4t(uint32_t addr, unsigned* r) {
    asm volatile("ldmatrix.sync.aligned.m8n8.x4.trans.shared.b16 {%0,%1,%2,%3}, [%4];"
        : "=r"(r[0]), "=r"(r[1]), "=r"(r[2]), "=r"(r[3]) : "r"(addr));
}
__device__ __forceinline__ void cpasync16(uint32_t dst, const void* src) {
    asm volatile("cp.async.cg.shared.global [%0], [%1], 16;"
        :: "r"(dst), "l"(__cvta_generic_to_global(src)));
}
#define CP_COMMIT asm volatile("cp.async.commit_group;" ::: "memory")

// ---------------- fused prep: rmsnorm#1 + pack qkv -----------------------------
__global__ void prep_kernel(const float* __restrict__ x, const float* __restrict__ ga,
                            __half* __restrict__ xn,
                            const float* __restrict__ wq, const float* __restrict__ wk,
                            const float* __restrict__ wv, __half* __restrict__ wqkv) {
    const int nW = DIMC * DIMC;
    int bid = blockIdx.x;
    int tid = threadIdx.x;
    if (bid < BT) {
        const float* xr = x + (size_t)bid * DIMC;
        float4 xv = *(const float4*)(xr + tid * 4);
        float s = xv.x * xv.x + xv.y * xv.y + xv.z * xv.z + xv.w * xv.w;
        #pragma unroll
        for (int off = 16; off; off >>= 1) s += __shfl_xor_sync(0xFFFFFFFFu, s, off);
        __shared__ float ws[8];
        __shared__ float snorm;
        if ((tid & 31) == 0) ws[tid >> 5] = s;
        __syncthreads();
        if (tid == 0) {
            float t = 0.f;
            #pragma unroll
            for (int i = 0; i < 8; i++) t += ws[i];
            snorm = rsqrtf(t * (1.0f / DIMC) + EPSV);
        }
        __syncthreads();
        float n = snorm;
        float4 gv = *(const float4*)(ga + tid * 4);
        uint2 u;
        u.x = h2pack(xv.x * n * gv.x, xv.y * n * gv.y);
        u.y = h2pack(xv.z * n * gv.z, xv.w * n * gv.w);
        *(uint2*)(xn + (size_t)bid * DIMC + tid * 4) = u;
    } else {
        int i = ((bid - BT) * 256 + tid) * 16;
        int w = i / nW, li = i - w * nW;
        const float* src = (w == 0) ? wq : (w == 1) ? wk : wv;
        float scale = (w == 0) ? 0.125f : 1.0f;
        int r = li >> 10, c = li & 1023;
        __half* drow = wqkv + (size_t)r * QKVD + w * DIMC + c;
        float4 v0 = *(const float4*)(src + li);
        float4 v1 = *(const float4*)(src + li + 4);
        float4 v2 = *(const float4*)(src + li + 8);
        float4 v3 = *(const float4*)(src + li + 12);
        uint4 a, b;
        a.x = h2pack(v0.x * scale, v0.y * scale); a.y = h2pack(v0.z * scale, v0.w * scale);
        a.z = h2pack(v1.x * scale, v1.y * scale); a.w = h2pack(v1.z * scale, v1.w * scale);
        b.x = h2pack(v2.x * scale, v2.y * scale); b.y = h2pack(v2.z * scale, v2.w * scale);
        b.z = h2pack(v3.x * scale, v3.y * scale); b.w = h2pack(v3.z * scale, v3.w * scale);
        *(uint4*)drow = a;
        *(uint4*)(drow + 8) = b;
    }
}

// ---------------- RMSNorm, half input + half output ----------------------------
__global__ void rmsnorm_h_kernel(const __half* __restrict__ x,
                                 const float* __restrict__ g,
                                 __half* __restrict__ y) {
    int row = blockIdx.x;
    int tid = threadIdx.x;
    const __half* xr = x + (size_t)row * DIMC;
    uint2 raw = *(const uint2*)(xr + tid * 4);
    float2 lo = __half22float2(*(__half2*)&raw.x);
    float2 hi = __half22float2(*(__half2*)&raw.y);
    float s = lo.x * lo.x + lo.y * lo.y + hi.x * hi.x + hi.y * hi.y;
    #pragma unroll
    for (int off = 16; off; off >>= 1) s += __shfl_xor_sync(0xFFFFFFFFu, s, off);
    __shared__ float ws[8];
    __shared__ float snorm;
    if ((tid & 31) == 0) ws[tid >> 5] = s;
    __syncthreads();
    if (tid == 0) {
        float t = 0.f;
        #pragma unroll
        for (int i = 0; i < 8; i++) t += ws[i];
        snorm = rsqrtf(t * (1.0f / DIMC) + EPSV);
    }
    __syncthreads();
    float n = snorm;
    float4 gv = *(const float4*)(g + tid * 4);
    uint2 u;
    u.x = h2pack(lo.x * n * gv.x, lo.y * n * gv.y);
    u.y = h2pack(hi.x * n * gv.z, hi.y * n * gv.w);
    *(uint2*)(y + (size_t)row * DIMC + tid * 4) = u;
}

// ---------------- FP16 GEMM 128x128, 256 thr, K-chunk 64, 3-stage (round-14) ---
#define GSTAGE 32768
#define G_SMEM (3 * GSTAGE)
// mode bits: 1 = silu, 2 = half output, 4 = residual is half
__global__ __launch_bounds__(256, 2)
void gemm_f16(const __half* __restrict__ A, const __half* __restrict__ B,
              float* __restrict__ C, const float* __restrict__ res,
              int M, int N, int K, int mode) {
    extern __shared__ char smc[];
    const uint32_t sbase = smem_u32(smc);
    const int tid = threadIdx.x;
    const int warp = tid >> 5, lane = tid & 31;
    const int lg = lane >> 2, ltg = lane & 3;
    const int wm = warp >> 2, wn = warp & 3;
    const int bm0 = blockIdx.y * 128, bn0 = blockIdx.x * 128;

    const int arow0 = tid >> 3, ac = tid & 7;
    const __half* Agp = A + (size_t)(bm0 + arow0) * K + ac * 8;
    const int asw = (ac * 16) ^ ((arow0 & 7) << 4);
    const int brow0 = tid >> 4, bc = tid & 15;
    const __half* Bgp = B + (size_t)brow0 * N + bn0 + bc * 8;
    const int bsw = (bc * 16) ^ ((brow0 & 7) << 4);

    const int mat = lane >> 3, mrow = lane & 7;
    int aoff[4], boff[2];
    #pragma unroll
    for (int mt = 0; mt < 4; mt++) {
        int row = wm * 64 + mt * 16 + (mat & 1) * 8 + mrow;
        aoff[mt] = row * 128 + (((mat >> 1) << 4) ^ ((row & 7) << 4));
    }
    #pragma unroll
    for (int p = 0; p < 2; p++) {
        int kr = (mat & 1) * 8 + mrow;
        int nb = wn * 64 + p * 32 + ((mat >> 1) << 4);
        boff[p] = kr * 256 + (nb ^ ((kr & 7) << 4));
    }

    float acc[4][4][4];
    #pragma unroll
    for (int mt = 0; mt < 4; mt++)
        #pragma unroll
        for (int nt = 0; nt < 4; nt++)
            #pragma unroll
            for (int r = 0; r < 4; r++) acc[mt][nt][r] = 0.f;

    auto loadAB = [&](int kt, int slot) {
        uint32_t da = sbase + slot * GSTAGE;
        uint32_t db = da + 16384;
        #pragma unroll
        for (int i = 0; i < 4; i++)
            cpasync16(da + (arow0 + i * 32) * 128 + asw,
                      Agp + (size_t)kt * 64 + (size_t)i * 32 * K);
        #pragma unroll
        for (int i = 0; i < 4; i++)
            cpasync16(db + (brow0 + i * 16) * 256 + bsw,
                      Bgp + (size_t)(kt * 64 + i * 16) * N);
    };

    const int nkt = K >> 6;
    loadAB(0, 0); CP_COMMIT;
    loadAB(1, 1); CP_COMMIT;

    int slot = 0;
    for (int kt = 0; kt < nkt; kt++) {
        asm volatile("cp.async.wait_group 1;" ::: "memory");
        __syncthreads();
        if (kt + 2 < nkt) {
            int s2 = slot + 2; if (s2 >= 3) s2 -= 3;
            loadAB(kt + 2, s2);
            CP_COMMIT;
        }
        uint32_t sa = sbase + slot * GSTAGE;
        uint32_t sb = sa + 16384;
        #pragma unroll
        for (int kk = 0; kk < 4; kk++) {
            unsigned af[4][4], bf[2][4];
            #pragma unroll
            for (int mt = 0; mt < 4; mt++)
                ldsm4(sa + (aoff[mt] ^ (kk << 5)), af[mt]);
            #pragma unroll
            for (int p = 0; p < 2; p++)
                ldsm4t(sb + boff[p] + (kk << 12), bf[p]);
            #pragma unroll
            for (int mt = 0; mt < 4; mt++)
                #pragma unroll
                for (int nt = 0; nt < 4; nt++)
                    mma16(acc[mt][nt], af[mt], &bf[nt >> 1][(nt & 1) * 2]);
        }
        if (++slot >= 3) slot = 0;
    }

    #pragma unroll
    for (int mt = 0; mt < 4; mt++) {
        #pragma unroll
        for (int half = 0; half < 2; half++) {
            int r = bm0 + wm * 64 + mt * 16 + lg + half * 8;
            #pragma unroll
            for (int nt = 0; nt < 4; nt++) {
                int c = bn0 + wn * 32 + nt * 8 + 2 * ltg;
                float v0 = acc[mt][nt][half * 2 + 0];
                float v1 = acc[mt][nt][half * 2 + 1];
                if (mode & 1) {
                    v0 = v0 / (1.f + __expf(-v0));
                    v1 = v1 / (1.f + __expf(-v1));
                }
                if (res) {
                    if (mode & 4) {
                        __half2 hv = *(const __half2*)((const __half*)res + (size_t)r * N + c);
                        float2 fv = __half22float2(hv);
                        v0 += fv.x; v1 += fv.y;
                    } else {
                        float2 rv = *(const float2*)(res + (size_t)r * N + c);
                        v0 += rv.x; v1 += rv.y;
                    }
                }
                if (mode & 2) {
                    *(unsigned*)((__half*)C + (size_t)r * N + c) = h2pack(v0, v1);
                } else {
                    *(float2*)(C + (size_t)r * N + c) = make_float2(v0, v1);
                }
            }
        }
    }
}

// ---------------- Flash attention + fused wo/w1/w2 conversion ------------------
#define ATT_NBLK (BB * NH * (TT / 128))      // 512
__global__ __launch_bounds__(256, 2)
void attn_cvt_f16(const __half* __restrict__ QKV, __half* __restrict__ O,
                  const float* __restrict__ wo, const float* __restrict__ w1,
                  const float* __restrict__ w2,
                  __half* __restrict__ dwo, __half* __restrict__ dw1,
                  __half* __restrict__ dw2) {
    __shared__ __align__(16) char smA[16384];
    int bid = blockIdx.x;
    int tid = threadIdx.x;

    if (bid >= ATT_NBLK) {
        const int nW = DIMC * DIMC, nW4 = DIMC * HID;
        int i = ((bid - ATT_NBLK) * 256 + tid) * 16;
        const float* src;
        __half* dst;
        int li;
        if (i < nW)            { src = wo; dst = dwo; li = i; }
        else if (i < nW + nW4) { src = w1; dst = dw1; li = i - nW; }
        else                   { src = w2; dst = dw2; li = i - nW - nW4; }
        float4 v0 = *(const float4*)(src + li);
        float4 v1 = *(const float4*)(src + li + 4);
        float4 v2 = *(const float4*)(src + li + 8);
        float4 v3 = *(const float4*)(src + li + 12);
        uint4 a, b;
        a.x = h2pack(v0.x, v0.y); a.y = h2pack(v0.z, v0.w);
        a.z = h2pack(v1.x, v1.y); a.w = h2pack(v1.z, v1.w);
        b.x = h2pack(v2.x, v2.y); b.y = h2pack(v2.z, v2.w);
        b.z = h2pack(v3.x, v3.y); b.w = h2pack(v3.z, v3.w);
        *(uint4*)(dst + li) = a;
        *(uint4*)(dst + li + 8) = b;
        return;
    }

    int bh = bid & 31;
    int qt = (TT / 128 - 1) - (bid >> 5);
    char* Ksc = smA;
    char* Vsc = smA + 8192;
    const uint32_t ksb = smem_u32(Ksc);
    const uint32_t vsb = smem_u32(Vsc);

    int b = bh >> 4, h = bh & 15;
    int q0 = qt * 128;
    int warp = tid >> 5, lane = tid & 31;
    int g = lane >> 2, tg = lane & 3;
    int r0l = warp * 16 + g;
    const int mat = lane >> 3, mrow = lane & 7;
    int rmax = q0 + warp * 16 + 15;

    const __half* Qb = QKV + ((size_t)(b * TT + q0)) * QKVD + h * HD;
    const __half* Kb = QKV + ((size_t)(b * TT)) * QKVD + DIMC + h * HD;
    const __half* Vb = QKV + ((size_t)(b * TT)) * QKVD + 2 * DIMC + h * HD;

    unsigned qa[4][4];
    #pragma unroll
    for (int kk = 0; kk < 4; kk++) {
        qa[kk][0] = *(const unsigned*)(Qb + (size_t)r0l * QKVD + kk * 16 + 2 * tg);
        qa[kk][1] = *(const unsigned*)(Qb + (size_t)(r0l + 8) * QKVD + kk * 16 + 2 * tg);
        qa[kk][2] = *(const unsigned*)(Qb + (size_t)r0l * QKVD + kk * 16 + 8 + 2 * tg);
        qa[kk][3] = *(const unsigned*)(Qb + (size_t)(r0l + 8) * QKVD + kk * 16 + 8 + 2 * tg);
    }

    int boffK[4], voff[4];
    #pragma unroll
    for (int p = 0; p < 4; p++) {
        int n = p * 16 + (mat >> 1) * 8 + mrow;
        boffK[p] = n * 128 + ((((unsigned)(mat & 1)) << 4) ^ ((n & 7) << 4));
        int sr = (mat & 1) * 8 + mrow;
        int db = (2 * p + (mat >> 1)) * 16;
        voff[p] = sr * 128 + (db ^ ((sr & 7) << 4));
    }

    float oacc[8][4];
    #pragma unroll
    for (int nt = 0; nt < 8; nt++)
        #pragma unroll
        for (int r = 0; r < 4; r++) oacc[nt][r] = 0.f;
    float m0 = -1e30f, m1 = -1e30f, l0 = 0.f, l1 = 0.f;
    int r0g = q0 + r0l, r1g = r0g + 8;

    int send = q0 + 64;
    for (int s0 = 0; s0 <= send; s0 += 64) {
        for (int i = tid; i < 512; i += 256) {
            int r = i >> 3, c = i & 7;
            int sw = (c * 16) ^ ((r & 7) << 4);
            *(uint4*)(Ksc + r * 128 + sw) =
                *(const uint4*)(Kb + (size_t)(s0 + r) * QKVD + c * 8);
            *(uint4*)(Vsc + r * 128 + sw) =
                *(const uint4*)(Vb + (size_t)(s0 + r) * QKVD + c * 8);
        }
        __syncthreads();

        if (s0 <= rmax) {
            float sc[8][4];
            #pragma unroll
            for (int nt = 0; nt < 8; nt++)
                #pragma unroll
                for (int r = 0; r < 4; r++) sc[nt][r] = 0.f;
            #pragma unroll
            for (int kk = 0; kk < 4; kk++) {
                #pragma unroll
                for (int p = 0; p < 4; p++) {
                    unsigned bf[4];
                    ldsm4(ksb + (boffK[p] ^ (kk << 5)), bf);
                    mma16(sc[2 * p], qa[kk], bf);
                    mma16(sc[2 * p + 1], qa[kk], bf + 2);
                }
            }

            if (s0 + 63 > r0g) {
                #pragma unroll
                for (int nt = 0; nt < 8; nt++) {
                    int j = s0 + nt * 8 + 2 * tg;
                    if (j     > r0g) sc[nt][0] = -1e30f;
                    if (j + 1 > r0g) sc[nt][1] = -1e30f;
                    if (j     > r1g) sc[nt][2] = -1e30f;
                    if (j + 1 > r1g) sc[nt][3] = -1e30f;
                }
            }

            float mx0 = -1e30f, mx1 = -1e30f;
            #pragma unroll
            for (int nt = 0; nt < 8; nt++) {
                mx0 = fmaxf(mx0, fmaxf(sc[nt][0], sc[nt][1]));
                mx1 = fmaxf(mx1, fmaxf(sc[nt][2], sc[nt][3]));
            }
            mx0 = fmaxf(mx0, __shfl_xor_sync(0xFFFFFFFFu, mx0, 1));
            mx0 = fmaxf(mx0, __shfl_xor_sync(0xFFFFFFFFu, mx0, 2));
            mx1 = fmaxf(mx1, __shfl_xor_sync(0xFFFFFFFFu, mx1, 1));
            mx1 = fmaxf(mx1, __shfl_xor_sync(0xFFFFFFFFu, mx1, 2));
            float mn0 = fmaxf(m0, mx0), mn1 = fmaxf(m1, mx1);
            float al0 = __expf(m0 - mn0), al1 = __expf(m1 - mn1);
            float s0r = 0.f, s1r = 0.f;
            #pragma unroll
            for (int nt = 0; nt < 8; nt++) {
                sc[nt][0] = __expf(sc[nt][0] - mn0);
                sc[nt][1] = __expf(sc[nt][1] - mn0);
                sc[nt][2] = __expf(sc[nt][2] - mn1);
                sc[nt][3] = __expf(sc[nt][3] - mn1);
                s0r += sc[nt][0] + sc[nt][1];
                s1r += sc[nt][2] + sc[nt][3];
            }
            s0r += __shfl_xor_sync(0xFFFFFFFFu, s0r, 1);
            s0r += __shfl_xor_sync(0xFFFFFFFFu, s0r, 2);
            s1r += __shfl_xor_sync(0xFFFFFFFFu, s1r, 1);
            s1r += __shfl_xor_sync(0xFFFFFFFFu, s1r, 2);
            l0 = l0 * al0 + s0r;
            l1 = l1 * al1 + s1r;
            m0 = mn0; m1 = mn1;
            #pragma unroll
            for (int nt = 0; nt < 8; nt++) {
                oacc[nt][0] *= al0; oacc[nt][1] *= al0;
                oacc[nt][2] *= al1; oacc[nt][3] *= al1;
            }

            #pragma unroll
            for (int kk = 0; kk < 4; kk++) {
                unsigned pa[4];
                pa[0] = h2pack(sc[2 * kk][0],     sc[2 * kk][1]);
                pa[1] = h2pack(sc[2 * kk][2],     sc[2 * kk][3]);
                pa[2] = h2pack(sc[2 * kk + 1][0], sc[2 * kk + 1][1]);
                pa[3] = h2pack(sc[2 * kk + 1][2], sc[2 * kk + 1][3]);
                #pragma unroll
                for (int p = 0; p < 4; p++) {
                    unsigned bf[4];
                    ldsm4t(vsb + voff[p] + (kk << 11), bf);
                    mma16(oacc[2 * p], pa, bf);
                    mma16(oacc[2 * p + 1], pa, bf + 2);
                }
            }
        }
        __syncthreads();
    }

    float il0 = 1.f / l0, il1 = 1.f / l1;
    __half* Ob = O + ((size_t)(b * TT + q0 + r0l)) * DIMC + h * HD;
    #pragma unroll
    for (int nt = 0; nt < 8; nt++) {
        *(unsigned*)(Ob + nt * 8 + 2 * tg) =
            h2pack(oacc[nt][0] * il0, oacc[nt][1] * il0);
        *(unsigned*)(Ob + (size_t)8 * DIMC + nt * 8 + 2 * tg) =
            h2pack(oacc[nt][2] * il1, oacc[nt][3] * il1);
    }
}

// ---------------- launcher ----------------------------------------------------
extern "C" void kernel_launch(void* const* d_in, const int* in_sizes, int n_in,
                              void* d_out, int out_size) {
    const float* x  = (const float*)d_in[0];
    const float* wq = (const float*)d_in[2];
    const float* wk = (const float*)d_in[3];
    const float* wv = (const float*)d_in[4];
    const float* wo = (const float*)d_in[5];
    const float* w1 = (const float*)d_in[6];
    const float* w2 = (const float*)d_in[7];
    const float* ga = (const float*)d_in[8];
    const float* gf = (const float*)d_in[9];
    float* out = (float*)d_out;

    __half *xn, *qkv, *ao, *hb, *x1h, *wqkv, *wou, *w1u, *w2u;
    cudaGetSymbolAddress((void**)&xn,   g_xn);
    cudaGetSymbolAddress((void**)&qkv,  g_qkv);
    cudaGetSymbolAddress((void**)&ao,   g_ao);
    cudaGetSymbolAddress((void**)&x1h,  g_x1);
    cudaGetSymbolAddress((void**)&hb,   g_h);
    cudaGetSymbolAddress((void**)&wqkv, g_wqkv);
    cudaGetSymbolAddress((void**)&wou,  g_wou);
    cudaGetSymbolAddress((void**)&w1u,  g_w1u);
    cudaGetSymbolAddress((void**)&w2u,  g_w2u);

    cudaFuncSetAttribute(gemm_f16,
                         cudaFuncAttributeMaxDynamicSharedMemorySize, G_SMEM);

    dim3 gQKV(QKVD / 128, BT / 128);  // (24, 32)
    dim3 gN1(DIMC / 128, BT / 128);   // (8, 32)
    dim3 gN4(HID  / 128, BT / 128);   // (32, 32)

    const int nW = DIMC * DIMC, nW4 = DIMC * HID;
    const int cvtBlocks = (nW + 2 * nW4) / 4096;       // 2304

    // 1: rmsnorm#1 + qkv pack
    prep_kernel<<<BT + (3 * nW) / 4096, 256>>>(x, ga, xn, wq, wk, wv, wqkv);
    // 2: fused QKV GEMM (half out)
    gemm_f16<<<gQKV, 256, G_SMEM>>>(xn, wqkv, (float*)qkv, nullptr, BT, QKVD, DIMC, 2);
    // 3: attention + wo/w1/w2 conversion (overlapped)
    attn_cvt_f16<<<ATT_NBLK + cvtBlocks, 256>>>(qkv, ao, wo, w1, w2, wou, w1u, w2u);
    // 4: x1(half) = x(fp32) + ao @ wo   [mode: half out]
    gemm_f16<<<gN1, 256, G_SMEM>>>(ao, wou, (float*)x1h, x, BT, DIMC, DIMC, 2);
    // 5: rmsnorm#2 (half in, half out)
    rmsnorm_h_kernel<<<BT, 256>>>(x1h, gf, xn);
    // 6: hb = silu(xn @ w1) [half out]
    gemm_f16<<<gN4, 256, G_SMEM>>>(xn, w1u, (float*)hb, nullptr, BT, HID, DIMC, 3);
    // 7: out(fp32) = x1(half) + hb @ w2  [mode: half residual]
    gemm_f16<<<gN1, 256, G_SMEM>>>(hb, w2u, out, (const float*)x1h, BT, DIMC, HID, 4);
}